// round 14
// baseline (speedup 1.0000x reference)
#include <cuda_runtime.h>
#include <cstdint>

// SupportLowRankRNN: B=32, T=1000, H=2048, I=4, R=2, O=2, S=2, G=8
#define TT       1000
#define HID      2048
#define NTHREADS 256
#define NWARPS   8
#define UNITS    8          // hidden units per thread
#define PAIRS    4          // float2 pairs per thread
#define NSLOT    8          // noise ring slots
#define PFD      4          // prefetch distance
#define ALPHA_F  0.2f
#define OMA_F    0.8f
#define SIG_F    0.05f
#define L2E2X    2.8853900817779268f  // 2*log2(e) -- state kept pre-scaled by this

// smem layout (floats)
#define SM_NOISE 0                         // 8 slots * 2048 = 16384
#define SM_IN    (NSLOT*HID)               // 4000 (input seq 1000*4)
#define SM_RED   (SM_IN + 4000)            // 2 parity * 8 float2 = 32 floats
#define SM_W     (SM_RED + 32)             // 192 staged weights
#define SM_FLOATS (SM_W + 192)
#define SMEM_BYTES (SM_FLOATS * 4)         // ~82.4 KB

// weight staging offsets inside SM_W
#define W_WI  0
#define W_M   64
#define W_N   96
#define W_WO  128
#define W_WIB 160
#define W_MB  168
#define W_NB  172
#define W_H0  176

// per-thread output partials: [b][t][tid][2]  (65.5 MB)
__device__ float g_scratch[(size_t)32 * TT * NTHREADS * 2];

__device__ __forceinline__ unsigned long long f2u(float2 v){ union{float2 f; unsigned long long u;} x; x.f=v; return x.u; }
__device__ __forceinline__ float2 u2f(unsigned long long u){ union{float2 f; unsigned long long u;} x; x.u=u; return x.f; }
__device__ __forceinline__ float2 ffma2(float2 a,float2 b,float2 c){
  unsigned long long D; asm("fma.rn.f32x2 %0,%1,%2,%3;":"=l"(D):"l"(f2u(a)),"l"(f2u(b)),"l"(f2u(c))); return u2f(D);
}
__device__ __forceinline__ float2 fmul2(float2 a,float2 b){
  unsigned long long D; asm("mul.rn.f32x2 %0,%1,%2;":"=l"(D):"l"(f2u(a)),"l"(f2u(b))); return u2f(D);
}
__device__ __forceinline__ float2 fadd2(float2 a,float2 b){
  unsigned long long D; asm("add.rn.f32x2 %0,%1,%2;":"=l"(D):"l"(f2u(a)),"l"(f2u(b))); return u2f(D);
}
__device__ __forceinline__ float ex2a(float x){ float y; asm("ex2.approx.f32 %0,%1;":"=f"(y):"f"(x)); return y; }
__device__ __forceinline__ float rcpa(float x){ float y; asm("rcp.approx.f32 %0,%1;":"=f"(y):"f"(x)); return y; }
__device__ __forceinline__ void cp16(uint32_t s, const void* g){
  asm volatile("cp.async.ca.shared.global [%0], [%1], 16;"::"r"(s),"l"(g));
}
#define CP_COMMIT() asm volatile("cp.async.commit_group;")
#define CP_WAIT3()  asm volatile("cp.async.wait_group 3;")

// 5-level butterfly on a PACKED float2 (2 SHFL + 1 fadd2 per level; halves pipeline)
__device__ __forceinline__ float2 warp_sum_pack(float2 v){
  #pragma unroll
  for (int o = 16; o > 0; o >>= 1) {
    float sx = __shfl_xor_sync(0xffffffffu, v.x, o);
    float sy = __shfl_xor_sync(0xffffffffu, v.y, o);
    v = fadd2(v, make_float2(sx, sy));
  }
  return v;
}

// re-pair two float2 accumulators into (a.x+a.y, b.x+b.y) with ONE fadd2
__device__ __forceinline__ float2 pair_sum(float2 a, float2 b){
  return fadd2(make_float2(a.x, b.x), make_float2(a.y, b.y));
}

// tanh from PRE-SCALED state H = 2*log2(e)*h: tanh(h) = 1 - 2/(1+2^H).
// ONE rcp per pair (batched reciprocal); no clamps (|h|<=O(5) under 0.8-contraction).
__device__ __forceinline__ float2 tanh2s(float2 H){
  float2 d = fadd2(make_float2(ex2a(H.x), ex2a(H.y)), make_float2(1.f, 1.f));
  float inv = rcpa(d.x * d.y);
  float s = -2.f * inv;
  return make_float2(fmaf(s, d.y, 1.f), fmaf(s, d.x, 1.f));
}

__global__ void __launch_bounds__(NTHREADS, 1)
rnn_main(const float* __restrict__ input,   // (32,1000,4)
         const float* __restrict__ noise,   // (32,1000,2048)
         const float* __restrict__ wi_w, const float* __restrict__ m_w,
         const float* __restrict__ n_w, const float* __restrict__ wo_w,
         const float* __restrict__ wi_b, const float* __restrict__ m_b,
         const float* __restrict__ n_b, const float* __restrict__ h0_w,
         const float* __restrict__ basis,   // (8,2048)
         const float* __restrict__ sup)     // (2,2048)
{
  const int b    = blockIdx.x;
  const int tid  = threadIdx.x;
  const int lane = tid & 31;
  const int warp = tid >> 5;
  const int u0   = tid * UNITS;

  extern __shared__ __align__(16) float sm[];
  float* s_noise = sm + SM_NOISE;
  float* s_in    = sm + SM_IN;
  float2* s_red2 = reinterpret_cast<float2*>(sm + SM_RED);   // [parity][8] float2
  float4* s_red4 = reinterpret_cast<float4*>(sm + SM_RED);   // [parity][4] float4
  float* s_w     = sm + SM_W;

  // ---- stage tiny weights to smem ----
  if (tid < 64)        s_w[tid] = wi_w[tid];
  else if (tid < 96)   s_w[tid] = m_w[tid - 64];
  else if (tid < 128)  s_w[tid] = n_w[tid - 96];
  else if (tid < 160)  s_w[tid] = wo_w[tid - 128];
  else if (tid < 168)  s_w[tid] = wi_b[tid - 160];
  else if (tid < 172)  s_w[tid] = m_b[tid - 168];
  else if (tid < 176)  s_w[tid] = n_b[tid - 172];
  else if (tid < 192)  s_w[tid] = h0_w[tid - 176];

  // ---- preload full input sequence (16KB) ----
  const float4* inb = reinterpret_cast<const float4*>(input + (size_t)b * (TT * 4));
  for (int i = tid; i < TT; i += NTHREADS)
    reinterpret_cast<float4*>(s_in)[i] = inb[i];

  // ---- noise cp.async prologue: slots 0..3 (distance-4 pipeline) ----
  const float* nbase = noise + (size_t)b * TT * HID + u0;
  uint32_t sn_u32 = (uint32_t)__cvta_generic_to_shared(s_noise + u0);
  #pragma unroll
  for (int ps = 0; ps < PFD; ps++) {
    cp16(sn_u32 + (uint32_t)ps * HID * 4,      nbase + (size_t)ps * HID);
    cp16(sn_u32 + (uint32_t)ps * HID * 4 + 16, nbase + (size_t)ps * HID + 4);
    CP_COMMIT();
  }

  __syncthreads();  // s_w + s_in ready

  // ---- per-unit params; packed float2 pairs.
  //      All additive-into-H quantities pre-scaled by C = 2*log2(e):
  //      wi (with alpha), m (with alpha), h0, and the sigma constant below.
  float2 wip[4][PAIRS], n0p[PAIRS], n1p[PAIRS], ma0p[PAIRS], ma1p[PAIRS],
         wo0p[PAIRS], wo1p[PAIRS], hh[PAIRS];
  {
    const float AC = ALPHA_F * L2E2X;
    float wia[4][UNITS], nn0[UNITS], nn1[UNITS], mm0[UNITS], mm1[UNITS],
          ww0[UNITS], ww1[UNITS], h0v[UNITS];
    #pragma unroll
    for (int j = 0; j < UNITS; j++) {
      const int h = u0 + j;
      float B[8];
      #pragma unroll
      for (int g = 0; g < 8; g++) B[g] = basis[g * HID + h];
      const float su0 = sup[h], su1 = sup[HID + h];
      #pragma unroll
      for (int x = 0; x < 4; x++) {
        float t0 = s_w[W_WIB + x*2 + 0], t1 = s_w[W_WIB + x*2 + 1];
        #pragma unroll
        for (int g = 0; g < 8; g++) { t0 += s_w[W_WI + x*16 + g]*B[g]; t1 += s_w[W_WI + x*16 + 8 + g]*B[g]; }
        wia[x][j] = AC * (t0*su0 + t1*su1);
      }
      #pragma unroll
      for (int r = 0; r < 2; r++) {
        float tm0 = s_w[W_MB + r*2 + 0], tm1 = s_w[W_MB + r*2 + 1];
        float tn0 = s_w[W_NB + r*2 + 0], tn1 = s_w[W_NB + r*2 + 1];
        #pragma unroll
        for (int g = 0; g < 8; g++) {
          tm0 += s_w[W_M + r*16 + g]*B[g];  tm1 += s_w[W_M + r*16 + 8 + g]*B[g];
          tn0 += s_w[W_N + r*16 + g]*B[g];  tn1 += s_w[W_N + r*16 + 8 + g]*B[g];
        }
        float mv = AC * (tm0*su0 + tm1*su1);
        float nv = tn0*su0 + tn1*su1;
        if (r == 0) { mm0[j] = mv; nn0[j] = nv; } else { mm1[j] = mv; nn1[j] = nv; }
      }
      #pragma unroll
      for (int o = 0; o < 2; o++) {
        float t0 = 0.f, t1 = 0.f;
        #pragma unroll
        for (int g = 0; g < 8; g++) { t0 += s_w[W_WO + o*16 + g]*B[g]; t1 += s_w[W_WO + o*16 + 8 + g]*B[g]; }
        float wv = t0*su0 + t1*su1;
        if (o == 0) ww0[j] = wv; else ww1[j] = wv;
      }
      {
        float t0 = 0.f, t1 = 0.f;
        #pragma unroll
        for (int g = 0; g < 8; g++) { t0 += s_w[W_H0 + g]*B[g]; t1 += s_w[W_H0 + 8 + g]*B[g]; }
        h0v[j] = L2E2X * (t0*su0 + t1*su1);
      }
    }
    #pragma unroll
    for (int p = 0; p < PAIRS; p++) {
      wip[0][p] = make_float2(wia[0][2*p], wia[0][2*p+1]);
      wip[1][p] = make_float2(wia[1][2*p], wia[1][2*p+1]);
      wip[2][p] = make_float2(wia[2][2*p], wia[2][2*p+1]);
      wip[3][p] = make_float2(wia[3][2*p], wia[3][2*p+1]);
      n0p[p]  = make_float2(nn0[2*p], nn0[2*p+1]);
      n1p[p]  = make_float2(nn1[2*p], nn1[2*p+1]);
      ma0p[p] = make_float2(mm0[2*p], mm0[2*p+1]);
      ma1p[p] = make_float2(mm1[2*p], mm1[2*p+1]);
      wo0p[p] = make_float2(ww0[2*p], ww0[2*p+1]);
      wo1p[p] = make_float2(ww1[2*p], ww1[2*p+1]);
      hh[p]   = make_float2(h0v[2*p], h0v[2*p+1]);
    }
  }

  // ---- initial pz from r_init = tanh(h0) (hh already pre-scaled) ----
  float2 pz;   // packed (z0-partial, z1-partial)
  {
    float2 az0 = make_float2(0,0), az1 = az0;
    #pragma unroll
    for (int p = 0; p < PAIRS; p++) {
      float2 r2 = tanh2s(hh[p]);
      az0 = ffma2(r2, n0p[p], az0);
      az1 = ffma2(r2, n1p[p], az1);
    }
    pz = pair_sum(az0, az1);
  }

  const float2 OMA2 = make_float2(OMA_F, OMA_F);
  const float2 SIG2 = make_float2(SIG_F * L2E2X, SIG_F * L2E2X);
  float2* scr = reinterpret_cast<float2*>(g_scratch) + (size_t)b * (TT * NTHREADS) + tid;

  // ---- main scan (unroll 8: parity + ring indices become compile-time) ----
  #pragma unroll 8
  for (int t = 0; t < TT; t++) {
    const int pb = t & 1;
    // packed z-butterfly over warp; all lanes get warp sums
    pz = warp_sum_pack(pz);
    if (lane == 0) s_red2[pb * 8 + warp] = pz;

    // ensure noise slot t complete (3 newer groups allowed: t+1..t+3)
    CP_WAIT3();
    const float* np = s_noise + (t & (NSLOT-1)) * HID + u0;
    float4 ga = *reinterpret_cast<const float4*>(np);
    float4 gb = *reinterpret_cast<const float4*>(np + 4);
    float4 xv = reinterpret_cast<const float4*>(s_in)[t];

    // z-independent precompute (off the critical chain)
    const float2 x0_2 = make_float2(xv.x, xv.x), x1_2 = make_float2(xv.y, xv.y);
    const float2 x2_2 = make_float2(xv.z, xv.z), x3_2 = make_float2(xv.w, xv.w);
    float2 gg[PAIRS] = { make_float2(ga.x, ga.y), make_float2(ga.z, ga.w),
                         make_float2(gb.x, gb.y), make_float2(gb.z, gb.w) };
    float2 pre[PAIRS];
    #pragma unroll
    for (int p = 0; p < PAIRS; p++) {
      float2 a = fmul2(SIG2, gg[p]);
      a = ffma2(OMA2, hh[p], a);
      a = ffma2(x0_2, wip[0][p], a);
      a = ffma2(x1_2, wip[1][p], a);
      a = ffma2(x2_2, wip[2][p], a);
      a = ffma2(x3_2, wip[3][p], a);
      pre[p] = a;
    }

    // prefetch noise slot t+4 BEFORE the barrier (slot last read at step t-4)
    int tp = (t + PFD < TT) ? (t + PFD) : (TT - 1);
    uint32_t soff = (uint32_t)(((t + PFD) & (NSLOT-1)) * HID * 4);
    cp16(sn_u32 + soff,      nbase + (size_t)tp * HID);
    cp16(sn_u32 + soff + 16, nbase + (size_t)tp * HID + 4);
    CP_COMMIT();

    __syncthreads();

    // stage-2: broadcast LDS of 8 warp partials (4 x float4) + 7-fadd2 tree
    float4 q0 = s_red4[pb*4 + 0], q1 = s_red4[pb*4 + 1];
    float4 q2 = s_red4[pb*4 + 2], q3 = s_red4[pb*4 + 3];
    float2 sA = fadd2(make_float2(q0.x, q0.y), make_float2(q0.z, q0.w));
    float2 sB = fadd2(make_float2(q1.x, q1.y), make_float2(q1.z, q1.w));
    float2 sC = fadd2(make_float2(q2.x, q2.y), make_float2(q2.z, q2.w));
    float2 sD = fadd2(make_float2(q3.x, q3.y), make_float2(q3.z, q3.w));
    float2 zz = fadd2(fadd2(sA, sB), fadd2(sC, sD));
    const float2 z0_2 = make_float2(zz.x, zz.x), z1_2 = make_float2(zz.y, zz.y);

    float2 az0 = make_float2(0,0), az1 = az0, ao0 = az0, ao1 = az0;
    #pragma unroll
    for (int p = 0; p < PAIRS; p++) {
      float2 tzz = ffma2(z1_2, ma1p[p], pre[p]);
      float2 acc = ffma2(z0_2, ma0p[p], tzz);
      hh[p] = acc;
      float2 r2 = tanh2s(acc);
      az0 = ffma2(r2, n0p[p], az0);
      az1 = ffma2(r2, n1p[p], az1);
      ao0 = ffma2(r2, wo0p[p], ao0);
      ao1 = ffma2(r2, wo1p[p], ao1);
    }
    pz = pair_sum(az0, az1);
    // per-thread packed output partial straight to scratch
    scr[(size_t)t * NTHREADS] = pair_sum(ao0, ao1);
  }
}

// pass 2: out[b,t,:] = sum over 256 threads of per-thread partials.
// one warp per (b,t): each lane sums 8 float2 (4 global float4 loads), then butterfly.
__global__ void __launch_bounds__(256, 8)
out_reduce(float* __restrict__ out)
{
  const int warp = threadIdx.x >> 5;
  const int lane = threadIdx.x & 31;
  const int i = blockIdx.x * 8 + warp;           // (b,t) pair, 32*1000 total
  if (i >= 32 * TT) return;
  const float4* p = reinterpret_cast<const float4*>(g_scratch + (size_t)i * (NTHREADS * 2)) + lane * 4;
  float4 a = p[0], c = p[1], d = p[2], e = p[3];
  float o0 = (a.x + a.z) + (c.x + c.z) + (d.x + d.z) + (e.x + e.z);
  float o1 = (a.y + a.w) + (c.y + c.w) + (d.y + d.w) + (e.y + e.w);
  #pragma unroll
  for (int o = 16; o > 0; o >>= 1) {
    o0 += __shfl_xor_sync(0xffffffffu, o0, o);
    o1 += __shfl_xor_sync(0xffffffffu, o1, o);
  }
  if (lane == 0)
    reinterpret_cast<float2*>(out)[i] = make_float2(o0, o1);
}

extern "C" void kernel_launch(void* const* d_in, const int* in_sizes, int n_in,
                              void* d_out, int out_size) {
  const float* input = (const float*)d_in[0];
  const float* noise = (const float*)d_in[1];
  const float* wi_w  = (const float*)d_in[2];
  const float* m_w   = (const float*)d_in[3];
  const float* n_w   = (const float*)d_in[4];
  const float* wo_w  = (const float*)d_in[5];
  const float* wi_b  = (const float*)d_in[6];
  const float* m_b   = (const float*)d_in[7];
  const float* n_b   = (const float*)d_in[8];
  const float* h0_w  = (const float*)d_in[9];
  const float* basis = (const float*)d_in[10];
  const float* sup   = (const float*)d_in[11];
  float* out = (float*)d_out;

  cudaFuncSetAttribute(rnn_main, cudaFuncAttributeMaxDynamicSharedMemorySize, SMEM_BYTES);
  rnn_main<<<32, NTHREADS, SMEM_BYTES>>>(input, noise, wi_w, m_w, n_w, wo_w,
                                         wi_b, m_b, n_b, h0_w, basis, sup);
  out_reduce<<<(32 * TT + 7) / 8, 256>>>(out);
}

// round 15
// speedup vs baseline: 1.0228x; 1.0228x over previous
#include <cuda_runtime.h>
#include <cstdint>

// SupportLowRankRNN: B=32, T=1000, H=2048, I=4, R=2, O=2, S=2, G=8
#define TT       1000
#define HID      2048
#define NTHREADS 256
#define NWARPS   8
#define UNITS    8          // hidden units per thread
#define PAIRS    4          // float2 pairs per thread
#define NSLOT    8          // noise ring slots
#define PFD      4          // prefetch distance
#define ALPHA_F  0.2f
#define OMA_F    0.8f
#define SIG_F    0.05f
#define L2E2X    2.8853900817779268f  // 2*log2(e) -- state kept pre-scaled by this

// smem layout (floats)
#define SM_NOISE 0                         // 8 slots * 2048 = 16384
#define SM_IN    (NSLOT*HID)               // 4000 (input seq 1000*4)
#define SM_RED   (SM_IN + 4000)            // 2 parity * 8 float2 = 32 floats
#define SM_W     (SM_RED + 32)             // 192 staged weights
#define SM_FLOATS (SM_W + 192)
#define SMEM_BYTES (SM_FLOATS * 4)         // ~82.4 KB

// weight staging offsets inside SM_W
#define W_WI  0
#define W_M   64
#define W_N   96
#define W_WO  128
#define W_WIB 160
#define W_MB  168
#define W_NB  172
#define W_H0  176

// per-thread output partials: [b][t][tid][2]  (65.5 MB)
__device__ float g_scratch[(size_t)32 * TT * NTHREADS * 2];

__device__ __forceinline__ unsigned long long f2u(float2 v){ union{float2 f; unsigned long long u;} x; x.f=v; return x.u; }
__device__ __forceinline__ float2 u2f(unsigned long long u){ union{float2 f; unsigned long long u;} x; x.u=u; return x.f; }
__device__ __forceinline__ float2 ffma2(float2 a,float2 b,float2 c){
  unsigned long long D; asm("fma.rn.f32x2 %0,%1,%2,%3;":"=l"(D):"l"(f2u(a)),"l"(f2u(b)),"l"(f2u(c))); return u2f(D);
}
__device__ __forceinline__ float2 fmul2(float2 a,float2 b){
  unsigned long long D; asm("mul.rn.f32x2 %0,%1,%2;":"=l"(D):"l"(f2u(a)),"l"(f2u(b))); return u2f(D);
}
__device__ __forceinline__ float2 fadd2(float2 a,float2 b){
  unsigned long long D; asm("add.rn.f32x2 %0,%1,%2;":"=l"(D):"l"(f2u(a)),"l"(f2u(b))); return u2f(D);
}
__device__ __forceinline__ float ex2a(float x){ float y; asm("ex2.approx.f32 %0,%1;":"=f"(y):"f"(x)); return y; }
__device__ __forceinline__ float rcpa(float x){ float y; asm("rcp.approx.f32 %0,%1;":"=f"(y):"f"(x)); return y; }
__device__ __forceinline__ void cp16(uint32_t s, const void* g){
  asm volatile("cp.async.ca.shared.global [%0], [%1], 16;"::"r"(s),"l"(g));
}
#define CP_COMMIT() asm volatile("cp.async.commit_group;")
#define CP_WAIT3()  asm volatile("cp.async.wait_group 3;")

// 5-level butterfly on 2 independent values (latencies pipeline across the pair)
__device__ __forceinline__ void warp_sum2(float& a, float& b){
  #pragma unroll
  for (int o = 16; o > 0; o >>= 1) {
    a += __shfl_xor_sync(0xffffffffu, a, o);
    b += __shfl_xor_sync(0xffffffffu, b, o);
  }
}

// tanh from PRE-SCALED state H = 2*log2(e)*h: tanh(h) = 1 - 2/(1+2^H).
// ONE rcp per pair (batched reciprocal); no clamps (|h|<=O(5) under 0.8-contraction).
__device__ __forceinline__ float2 tanh2s(float2 H){
  float2 d = fadd2(make_float2(ex2a(H.x), ex2a(H.y)), make_float2(1.f, 1.f));
  float inv = rcpa(d.x * d.y);
  float s = -2.f * inv;
  return make_float2(fmaf(s, d.y, 1.f), fmaf(s, d.x, 1.f));
}

__global__ void __launch_bounds__(NTHREADS, 1)
rnn_main(const float* __restrict__ input,   // (32,1000,4)
         const float* __restrict__ noise,   // (32,1000,2048)
         const float* __restrict__ wi_w, const float* __restrict__ m_w,
         const float* __restrict__ n_w, const float* __restrict__ wo_w,
         const float* __restrict__ wi_b, const float* __restrict__ m_b,
         const float* __restrict__ n_b, const float* __restrict__ h0_w,
         const float* __restrict__ basis,   // (8,2048)
         const float* __restrict__ sup)     // (2,2048)
{
  const int b    = blockIdx.x;
  const int tid  = threadIdx.x;
  const int lane = tid & 31;
  const int warp = tid >> 5;
  const int u0   = tid * UNITS;

  extern __shared__ __align__(16) float sm[];
  float* s_noise = sm + SM_NOISE;
  float* s_in    = sm + SM_IN;
  float2* s_red2 = reinterpret_cast<float2*>(sm + SM_RED);   // [parity][8] float2
  float4* s_red4 = reinterpret_cast<float4*>(sm + SM_RED);   // [parity][4] float4
  float* s_w     = sm + SM_W;

  // ---- stage tiny weights to smem ----
  if (tid < 64)        s_w[tid] = wi_w[tid];
  else if (tid < 96)   s_w[tid] = m_w[tid - 64];
  else if (tid < 128)  s_w[tid] = n_w[tid - 96];
  else if (tid < 160)  s_w[tid] = wo_w[tid - 128];
  else if (tid < 168)  s_w[tid] = wi_b[tid - 160];
  else if (tid < 172)  s_w[tid] = m_b[tid - 168];
  else if (tid < 176)  s_w[tid] = n_b[tid - 172];
  else if (tid < 192)  s_w[tid] = h0_w[tid - 176];

  // ---- preload full input sequence (16KB) ----
  const float4* inb = reinterpret_cast<const float4*>(input + (size_t)b * (TT * 4));
  for (int i = tid; i < TT; i += NTHREADS)
    reinterpret_cast<float4*>(s_in)[i] = inb[i];

  // ---- noise cp.async prologue: slots 0..3 (distance-4 pipeline) ----
  const float* nbase = noise + (size_t)b * TT * HID + u0;
  uint32_t sn_u32 = (uint32_t)__cvta_generic_to_shared(s_noise + u0);
  #pragma unroll
  for (int ps = 0; ps < PFD; ps++) {
    cp16(sn_u32 + (uint32_t)ps * HID * 4,      nbase + (size_t)ps * HID);
    cp16(sn_u32 + (uint32_t)ps * HID * 4 + 16, nbase + (size_t)ps * HID + 4);
    CP_COMMIT();
  }

  __syncthreads();  // s_w + s_in ready

  // ---- per-unit params; packed float2 pairs.
  //      All additive-into-H quantities pre-scaled by C = 2*log2(e):
  //      wi (with alpha), m (with alpha), h0, and the sigma constant below.
  float2 wip[4][PAIRS], n0p[PAIRS], n1p[PAIRS], ma0p[PAIRS], ma1p[PAIRS],
         wo0p[PAIRS], wo1p[PAIRS], hh[PAIRS];
  {
    const float AC = ALPHA_F * L2E2X;
    float wia[4][UNITS], nn0[UNITS], nn1[UNITS], mm0[UNITS], mm1[UNITS],
          ww0[UNITS], ww1[UNITS], h0v[UNITS];
    #pragma unroll
    for (int j = 0; j < UNITS; j++) {
      const int h = u0 + j;
      float B[8];
      #pragma unroll
      for (int g = 0; g < 8; g++) B[g] = basis[g * HID + h];
      const float su0 = sup[h], su1 = sup[HID + h];
      #pragma unroll
      for (int x = 0; x < 4; x++) {
        float t0 = s_w[W_WIB + x*2 + 0], t1 = s_w[W_WIB + x*2 + 1];
        #pragma unroll
        for (int g = 0; g < 8; g++) { t0 += s_w[W_WI + x*16 + g]*B[g]; t1 += s_w[W_WI + x*16 + 8 + g]*B[g]; }
        wia[x][j] = AC * (t0*su0 + t1*su1);
      }
      #pragma unroll
      for (int r = 0; r < 2; r++) {
        float tm0 = s_w[W_MB + r*2 + 0], tm1 = s_w[W_MB + r*2 + 1];
        float tn0 = s_w[W_NB + r*2 + 0], tn1 = s_w[W_NB + r*2 + 1];
        #pragma unroll
        for (int g = 0; g < 8; g++) {
          tm0 += s_w[W_M + r*16 + g]*B[g];  tm1 += s_w[W_M + r*16 + 8 + g]*B[g];
          tn0 += s_w[W_N + r*16 + g]*B[g];  tn1 += s_w[W_N + r*16 + 8 + g]*B[g];
        }
        float mv = AC * (tm0*su0 + tm1*su1);
        float nv = tn0*su0 + tn1*su1;
        if (r == 0) { mm0[j] = mv; nn0[j] = nv; } else { mm1[j] = mv; nn1[j] = nv; }
      }
      #pragma unroll
      for (int o = 0; o < 2; o++) {
        float t0 = 0.f, t1 = 0.f;
        #pragma unroll
        for (int g = 0; g < 8; g++) { t0 += s_w[W_WO + o*16 + g]*B[g]; t1 += s_w[W_WO + o*16 + 8 + g]*B[g]; }
        float wv = t0*su0 + t1*su1;
        if (o == 0) ww0[j] = wv; else ww1[j] = wv;
      }
      {
        float t0 = 0.f, t1 = 0.f;
        #pragma unroll
        for (int g = 0; g < 8; g++) { t0 += s_w[W_H0 + g]*B[g]; t1 += s_w[W_H0 + 8 + g]*B[g]; }
        h0v[j] = L2E2X * (t0*su0 + t1*su1);
      }
    }
    #pragma unroll
    for (int p = 0; p < PAIRS; p++) {
      wip[0][p] = make_float2(wia[0][2*p], wia[0][2*p+1]);
      wip[1][p] = make_float2(wia[1][2*p], wia[1][2*p+1]);
      wip[2][p] = make_float2(wia[2][2*p], wia[2][2*p+1]);
      wip[3][p] = make_float2(wia[3][2*p], wia[3][2*p+1]);
      n0p[p]  = make_float2(nn0[2*p], nn0[2*p+1]);
      n1p[p]  = make_float2(nn1[2*p], nn1[2*p+1]);
      ma0p[p] = make_float2(mm0[2*p], mm0[2*p+1]);
      ma1p[p] = make_float2(mm1[2*p], mm1[2*p+1]);
      wo0p[p] = make_float2(ww0[2*p], ww0[2*p+1]);
      wo1p[p] = make_float2(ww1[2*p], ww1[2*p+1]);
      hh[p]   = make_float2(h0v[2*p], h0v[2*p+1]);
    }
  }

  // ---- initial pz from r_init = tanh(h0) (hh already pre-scaled) ----
  float pz0, pz1;
  {
    float2 az0 = make_float2(0,0), az1 = az0;
    #pragma unroll
    for (int p = 0; p < PAIRS; p++) {
      float2 r2 = tanh2s(hh[p]);
      az0 = ffma2(r2, n0p[p], az0);
      az1 = ffma2(r2, n1p[p], az1);
    }
    pz0 = az0.x + az0.y; pz1 = az1.x + az1.y;
  }

  const float2 OMA2 = make_float2(OMA_F, OMA_F);
  const float2 SIG2 = make_float2(SIG_F * L2E2X, SIG_F * L2E2X);
  float2* scr = reinterpret_cast<float2*>(g_scratch) + (size_t)b * (TT * NTHREADS) + tid;

  // ---- main scan (unroll 8: parity + ring indices become compile-time) ----
  #pragma unroll 8
  for (int t = 0; t < TT; t++) {
    const int pb = t & 1;
    // z-butterfly over warp; all lanes get warp sums
    warp_sum2(pz0, pz1);
    if (lane == 0) s_red2[pb * 8 + warp] = make_float2(pz0, pz1);

    // ensure noise slot t complete (3 newer groups allowed: t+1..t+3)
    CP_WAIT3();
    const float* np = s_noise + (t & (NSLOT-1)) * HID + u0;
    float4 ga = *reinterpret_cast<const float4*>(np);
    float4 gb = *reinterpret_cast<const float4*>(np + 4);
    float4 xv = reinterpret_cast<const float4*>(s_in)[t];

    // z-independent precompute (off the critical chain)
    const float2 x0_2 = make_float2(xv.x, xv.x), x1_2 = make_float2(xv.y, xv.y);
    const float2 x2_2 = make_float2(xv.z, xv.z), x3_2 = make_float2(xv.w, xv.w);
    float2 gg[PAIRS] = { make_float2(ga.x, ga.y), make_float2(ga.z, ga.w),
                         make_float2(gb.x, gb.y), make_float2(gb.z, gb.w) };
    float2 pre[PAIRS];
    #pragma unroll
    for (int p = 0; p < PAIRS; p++) {
      float2 a = fmul2(SIG2, gg[p]);
      a = ffma2(OMA2, hh[p], a);
      a = ffma2(x0_2, wip[0][p], a);
      a = ffma2(x1_2, wip[1][p], a);
      a = ffma2(x2_2, wip[2][p], a);
      a = ffma2(x3_2, wip[3][p], a);
      pre[p] = a;
    }

    // prefetch noise slot t+4 BEFORE the barrier (slot last read at step t-4)
    int tp = (t + PFD < TT) ? (t + PFD) : (TT - 1);
    uint32_t soff = (uint32_t)(((t + PFD) & (NSLOT-1)) * HID * 4);
    cp16(sn_u32 + soff,      nbase + (size_t)tp * HID);
    cp16(sn_u32 + soff + 16, nbase + (size_t)tp * HID + 4);
    CP_COMMIT();

    __syncthreads();

    // stage-2: broadcast LDS of 8 warp partials (4 x float4) + 7-fadd2 tree
    float4 q0 = s_red4[pb*4 + 0], q1 = s_red4[pb*4 + 1];
    float4 q2 = s_red4[pb*4 + 2], q3 = s_red4[pb*4 + 3];
    float2 sA = fadd2(make_float2(q0.x, q0.y), make_float2(q0.z, q0.w));
    float2 sB = fadd2(make_float2(q1.x, q1.y), make_float2(q1.z, q1.w));
    float2 sC = fadd2(make_float2(q2.x, q2.y), make_float2(q2.z, q2.w));
    float2 sD = fadd2(make_float2(q3.x, q3.y), make_float2(q3.z, q3.w));
    float2 zz = fadd2(fadd2(sA, sB), fadd2(sC, sD));
    const float2 z0_2 = make_float2(zz.x, zz.x), z1_2 = make_float2(zz.y, zz.y);

    float2 az0 = make_float2(0,0), az1 = az0, ao0 = az0, ao1 = az0;
    #pragma unroll
    for (int p = 0; p < PAIRS; p++) {
      float2 tzz = ffma2(z1_2, ma1p[p], pre[p]);
      float2 acc = ffma2(z0_2, ma0p[p], tzz);
      hh[p] = acc;
      float2 r2 = tanh2s(acc);
      az0 = ffma2(r2, n0p[p], az0);
      az1 = ffma2(r2, n1p[p], az1);
      ao0 = ffma2(r2, wo0p[p], ao0);
      ao1 = ffma2(r2, wo1p[p], ao1);
    }
    pz0 = az0.x + az0.y; pz1 = az1.x + az1.y;
    // per-thread output partial straight to scratch (no in-loop reduction)
    scr[(size_t)t * NTHREADS] = make_float2(ao0.x + ao0.y, ao1.x + ao1.y);
  }
}

// pass 2: out[b,t,:] = sum over 256 threads of per-thread partials.
// one warp per (b,t): each lane sums 8 float2 (4 global float4 loads), then butterfly.
__global__ void __launch_bounds__(256, 8)
out_reduce(float* __restrict__ out)
{
  const int warp = threadIdx.x >> 5;
  const int lane = threadIdx.x & 31;
  const int i = blockIdx.x * 8 + warp;           // (b,t) pair, 32*1000 total
  if (i >= 32 * TT) return;
  const float4* p = reinterpret_cast<const float4*>(g_scratch + (size_t)i * (NTHREADS * 2)) + lane * 4;
  float4 a = p[0], c = p[1], d = p[2], e = p[3];
  float o0 = (a.x + a.z) + (c.x + c.z) + (d.x + d.z) + (e.x + e.z);
  float o1 = (a.y + a.w) + (c.y + c.w) + (d.y + d.w) + (e.y + e.w);
  #pragma unroll
  for (int o = 16; o > 0; o >>= 1) {
    o0 += __shfl_xor_sync(0xffffffffu, o0, o);
    o1 += __shfl_xor_sync(0xffffffffu, o1, o);
  }
  if (lane == 0)
    reinterpret_cast<float2*>(out)[i] = make_float2(o0, o1);
}

extern "C" void kernel_launch(void* const* d_in, const int* in_sizes, int n_in,
                              void* d_out, int out_size) {
  const float* input = (const float*)d_in[0];
  const float* noise = (const float*)d_in[1];
  const float* wi_w  = (const float*)d_in[2];
  const float* m_w   = (const float*)d_in[3];
  const float* n_w   = (const float*)d_in[4];
  const float* wo_w  = (const float*)d_in[5];
  const float* wi_b  = (const float*)d_in[6];
  const float* m_b   = (const float*)d_in[7];
  const float* n_b   = (const float*)d_in[8];
  const float* h0_w  = (const float*)d_in[9];
  const float* basis = (const float*)d_in[10];
  const float* sup   = (const float*)d_in[11];
  float* out = (float*)d_out;

  cudaFuncSetAttribute(rnn_main, cudaFuncAttributeMaxDynamicSharedMemorySize, SMEM_BYTES);
  rnn_main<<<32, NTHREADS, SMEM_BYTES>>>(input, noise, wi_w, m_w, n_w, wo_w,
                                         wi_b, m_b, n_b, h0_w, basis, sup);
  out_reduce<<<(32 * TT + 7) / 8, 256>>>(out);
}

// round 16
// speedup vs baseline: 1.0251x; 1.0022x over previous
#include <cuda_runtime.h>
#include <cstdint>

// SupportLowRankRNN: B=32, T=1000, H=2048, I=4, R=2, O=2, S=2, G=8
#define TT       1000
#define HID      2048
#define NTHREADS 256
#define NWARPS   8
#define UNITS    8          // hidden units per thread
#define PAIRS    4          // float2 pairs per thread
#define NSLOT    8          // noise ring slots
#define PFD      4          // prefetch distance
#define ALPHA_F  0.2f
#define OMA_F    0.8f
#define SIG_F    0.05f
#define L2E2X    2.8853900817779268f  // 2*log2(e) -- state kept pre-scaled by this

// smem layout (floats)
#define SM_NOISE 0                         // 8 slots * 2048 = 16384
#define SM_IN    (NSLOT*HID)               // 4000 (input seq 1000*4)
#define SM_RED   (SM_IN + 4000)            // 2 parity * 8 float2 = 32 floats
#define SM_W     (SM_RED + 32)             // 192 staged weights
#define SM_FLOATS (SM_W + 192)
#define SMEM_BYTES (SM_FLOATS * 4)         // ~82.4 KB

// weight staging offsets inside SM_W
#define W_WI  0
#define W_M   64
#define W_N   96
#define W_WO  128
#define W_WIB 160
#define W_MB  168
#define W_NB  172
#define W_H0  176

// per-thread output partials: [b][t][tid][2]  (65.5 MB)
__device__ float g_scratch[(size_t)32 * TT * NTHREADS * 2];

__device__ __forceinline__ unsigned long long f2u(float2 v){ union{float2 f; unsigned long long u;} x; x.f=v; return x.u; }
__device__ __forceinline__ float2 u2f(unsigned long long u){ union{float2 f; unsigned long long u;} x; x.u=u; return x.f; }
__device__ __forceinline__ float2 ffma2(float2 a,float2 b,float2 c){
  unsigned long long D; asm("fma.rn.f32x2 %0,%1,%2,%3;":"=l"(D):"l"(f2u(a)),"l"(f2u(b)),"l"(f2u(c))); return u2f(D);
}
__device__ __forceinline__ float2 fmul2(float2 a,float2 b){
  unsigned long long D; asm("mul.rn.f32x2 %0,%1,%2;":"=l"(D):"l"(f2u(a)),"l"(f2u(b))); return u2f(D);
}
__device__ __forceinline__ float2 fadd2(float2 a,float2 b){
  unsigned long long D; asm("add.rn.f32x2 %0,%1,%2;":"=l"(D):"l"(f2u(a)),"l"(f2u(b))); return u2f(D);
}
__device__ __forceinline__ float ex2a(float x){ float y; asm("ex2.approx.f32 %0,%1;":"=f"(y):"f"(x)); return y; }
__device__ __forceinline__ float rcpa(float x){ float y; asm("rcp.approx.f32 %0,%1;":"=f"(y):"f"(x)); return y; }
__device__ __forceinline__ void cp16(uint32_t s, const void* g){
  asm volatile("cp.async.ca.shared.global [%0], [%1], 16;"::"r"(s),"l"(g));
}
#define CP_COMMIT() asm volatile("cp.async.commit_group;")
#define CP_WAIT3()  asm volatile("cp.async.wait_group 3;")

// 5-level butterfly on 2 independent values (latencies pipeline across the pair)
__device__ __forceinline__ void warp_sum2(float& a, float& b){
  #pragma unroll
  for (int o = 16; o > 0; o >>= 1) {
    a += __shfl_xor_sync(0xffffffffu, a, o);
    b += __shfl_xor_sync(0xffffffffu, b, o);
  }
}

// tanh from PRE-SCALED state H = 2*log2(e)*h: tanh(h) = 1 - 2/(1+2^H).
// ONE rcp per pair (batched reciprocal); no clamps (|h|<=O(5) under 0.8-contraction).
__device__ __forceinline__ float2 tanh2s(float2 H){
  float2 d = fadd2(make_float2(ex2a(H.x), ex2a(H.y)), make_float2(1.f, 1.f));
  float inv = rcpa(d.x * d.y);
  float s = -2.f * inv;
  return make_float2(fmaf(s, d.y, 1.f), fmaf(s, d.x, 1.f));
}

__global__ void __launch_bounds__(NTHREADS, 1)
rnn_main(const float* __restrict__ input,   // (32,1000,4)
         const float* __restrict__ noise,   // (32,1000,2048)
         const float* __restrict__ wi_w, const float* __restrict__ m_w,
         const float* __restrict__ n_w, const float* __restrict__ wo_w,
         const float* __restrict__ wi_b, const float* __restrict__ m_b,
         const float* __restrict__ n_b, const float* __restrict__ h0_w,
         const float* __restrict__ basis,   // (8,2048)
         const float* __restrict__ sup)     // (2,2048)
{
  const int b    = blockIdx.x;
  const int tid  = threadIdx.x;
  const int lane = tid & 31;
  const int warp = tid >> 5;
  const int u0   = tid * UNITS;

  extern __shared__ __align__(16) float sm[];
  float* s_noise = sm + SM_NOISE;
  float* s_in    = sm + SM_IN;
  float2* s_red2 = reinterpret_cast<float2*>(sm + SM_RED);   // [parity][8] float2
  float4* s_red4 = reinterpret_cast<float4*>(sm + SM_RED);   // [parity][4] float4
  float* s_w     = sm + SM_W;

  // ---- stage tiny weights to smem ----
  if (tid < 64)        s_w[tid] = wi_w[tid];
  else if (tid < 96)   s_w[tid] = m_w[tid - 64];
  else if (tid < 128)  s_w[tid] = n_w[tid - 96];
  else if (tid < 160)  s_w[tid] = wo_w[tid - 128];
  else if (tid < 168)  s_w[tid] = wi_b[tid - 160];
  else if (tid < 172)  s_w[tid] = m_b[tid - 168];
  else if (tid < 176)  s_w[tid] = n_b[tid - 172];
  else if (tid < 192)  s_w[tid] = h0_w[tid - 176];

  // ---- preload full input sequence (16KB) ----
  const float4* inb = reinterpret_cast<const float4*>(input + (size_t)b * (TT * 4));
  for (int i = tid; i < TT; i += NTHREADS)
    reinterpret_cast<float4*>(s_in)[i] = inb[i];

  // ---- noise cp.async prologue: slots 0..3 (distance-4 pipeline) ----
  const float* nbase = noise + (size_t)b * TT * HID + u0;
  uint32_t sn_u32 = (uint32_t)__cvta_generic_to_shared(s_noise + u0);
  #pragma unroll
  for (int ps = 0; ps < PFD; ps++) {
    cp16(sn_u32 + (uint32_t)ps * HID * 4,      nbase + (size_t)ps * HID);
    cp16(sn_u32 + (uint32_t)ps * HID * 4 + 16, nbase + (size_t)ps * HID + 4);
    CP_COMMIT();
  }

  __syncthreads();  // s_w + s_in ready

  // ---- per-unit params; packed float2 pairs.
  //      All additive-into-H quantities pre-scaled by C = 2*log2(e):
  //      wi (with alpha), m (with alpha), h0, and the sigma constant below.
  float2 wip[4][PAIRS], n0p[PAIRS], n1p[PAIRS], ma0p[PAIRS], ma1p[PAIRS],
         wo0p[PAIRS], wo1p[PAIRS], hh[PAIRS];
  {
    const float AC = ALPHA_F * L2E2X;
    float wia[4][UNITS], nn0[UNITS], nn1[UNITS], mm0[UNITS], mm1[UNITS],
          ww0[UNITS], ww1[UNITS], h0v[UNITS];
    #pragma unroll
    for (int j = 0; j < UNITS; j++) {
      const int h = u0 + j;
      float B[8];
      #pragma unroll
      for (int g = 0; g < 8; g++) B[g] = basis[g * HID + h];
      const float su0 = sup[h], su1 = sup[HID + h];
      #pragma unroll
      for (int x = 0; x < 4; x++) {
        float t0 = s_w[W_WIB + x*2 + 0], t1 = s_w[W_WIB + x*2 + 1];
        #pragma unroll
        for (int g = 0; g < 8; g++) { t0 += s_w[W_WI + x*16 + g]*B[g]; t1 += s_w[W_WI + x*16 + 8 + g]*B[g]; }
        wia[x][j] = AC * (t0*su0 + t1*su1);
      }
      #pragma unroll
      for (int r = 0; r < 2; r++) {
        float tm0 = s_w[W_MB + r*2 + 0], tm1 = s_w[W_MB + r*2 + 1];
        float tn0 = s_w[W_NB + r*2 + 0], tn1 = s_w[W_NB + r*2 + 1];
        #pragma unroll
        for (int g = 0; g < 8; g++) {
          tm0 += s_w[W_M + r*16 + g]*B[g];  tm1 += s_w[W_M + r*16 + 8 + g]*B[g];
          tn0 += s_w[W_N + r*16 + g]*B[g];  tn1 += s_w[W_N + r*16 + 8 + g]*B[g];
        }
        float mv = AC * (tm0*su0 + tm1*su1);
        float nv = tn0*su0 + tn1*su1;
        if (r == 0) { mm0[j] = mv; nn0[j] = nv; } else { mm1[j] = mv; nn1[j] = nv; }
      }
      #pragma unroll
      for (int o = 0; o < 2; o++) {
        float t0 = 0.f, t1 = 0.f;
        #pragma unroll
        for (int g = 0; g < 8; g++) { t0 += s_w[W_WO + o*16 + g]*B[g]; t1 += s_w[W_WO + o*16 + 8 + g]*B[g]; }
        float wv = t0*su0 + t1*su1;
        if (o == 0) ww0[j] = wv; else ww1[j] = wv;
      }
      {
        float t0 = 0.f, t1 = 0.f;
        #pragma unroll
        for (int g = 0; g < 8; g++) { t0 += s_w[W_H0 + g]*B[g]; t1 += s_w[W_H0 + 8 + g]*B[g]; }
        h0v[j] = L2E2X * (t0*su0 + t1*su1);
      }
    }
    #pragma unroll
    for (int p = 0; p < PAIRS; p++) {
      wip[0][p] = make_float2(wia[0][2*p], wia[0][2*p+1]);
      wip[1][p] = make_float2(wia[1][2*p], wia[1][2*p+1]);
      wip[2][p] = make_float2(wia[2][2*p], wia[2][2*p+1]);
      wip[3][p] = make_float2(wia[3][2*p], wia[3][2*p+1]);
      n0p[p]  = make_float2(nn0[2*p], nn0[2*p+1]);
      n1p[p]  = make_float2(nn1[2*p], nn1[2*p+1]);
      ma0p[p] = make_float2(mm0[2*p], mm0[2*p+1]);
      ma1p[p] = make_float2(mm1[2*p], mm1[2*p+1]);
      wo0p[p] = make_float2(ww0[2*p], ww0[2*p+1]);
      wo1p[p] = make_float2(ww1[2*p], ww1[2*p+1]);
      hh[p]   = make_float2(h0v[2*p], h0v[2*p+1]);
    }
  }

  // ---- initial pz from r_init = tanh(h0) (hh already pre-scaled) ----
  float pz0, pz1;
  {
    float2 az0 = make_float2(0,0), az1 = az0;
    #pragma unroll
    for (int p = 0; p < PAIRS; p++) {
      float2 r2 = tanh2s(hh[p]);
      az0 = ffma2(r2, n0p[p], az0);
      az1 = ffma2(r2, n1p[p], az1);
    }
    pz0 = az0.x + az0.y; pz1 = az1.x + az1.y;
  }

  const float2 OMA2 = make_float2(OMA_F, OMA_F);
  const float2 SIG2 = make_float2(SIG_F * L2E2X, SIG_F * L2E2X);
  float2* scr = reinterpret_cast<float2*>(g_scratch) + (size_t)b * (TT * NTHREADS) + tid;

  // ---- main scan (unroll 8: parity + ring indices become compile-time) ----
  #pragma unroll 8
  for (int t = 0; t < TT; t++) {
    const int pb = t & 1;
    // z-butterfly over warp; all lanes get warp sums
    warp_sum2(pz0, pz1);
    if (lane == 0) s_red2[pb * 8 + warp] = make_float2(pz0, pz1);

    // ensure noise slot t complete (3 newer groups allowed: t+1..t+3)
    CP_WAIT3();
    const float* np = s_noise + (t & (NSLOT-1)) * HID + u0;
    float4 ga = *reinterpret_cast<const float4*>(np);
    float4 gb = *reinterpret_cast<const float4*>(np + 4);
    float4 xv = reinterpret_cast<const float4*>(s_in)[t];

    // z-independent precompute (off the critical chain)
    const float2 x0_2 = make_float2(xv.x, xv.x), x1_2 = make_float2(xv.y, xv.y);
    const float2 x2_2 = make_float2(xv.z, xv.z), x3_2 = make_float2(xv.w, xv.w);
    float2 gg[PAIRS] = { make_float2(ga.x, ga.y), make_float2(ga.z, ga.w),
                         make_float2(gb.x, gb.y), make_float2(gb.z, gb.w) };
    float2 pre[PAIRS];
    #pragma unroll
    for (int p = 0; p < PAIRS; p++) {
      float2 a = fmul2(SIG2, gg[p]);
      a = ffma2(OMA2, hh[p], a);
      a = ffma2(x0_2, wip[0][p], a);
      a = ffma2(x1_2, wip[1][p], a);
      a = ffma2(x2_2, wip[2][p], a);
      a = ffma2(x3_2, wip[3][p], a);
      pre[p] = a;
    }

    // prefetch noise slot t+4 BEFORE the barrier (slot last read at step t-4)
    int tp = (t + PFD < TT) ? (t + PFD) : (TT - 1);
    uint32_t soff = (uint32_t)(((t + PFD) & (NSLOT-1)) * HID * 4);
    cp16(sn_u32 + soff,      nbase + (size_t)tp * HID);
    cp16(sn_u32 + soff + 16, nbase + (size_t)tp * HID + 4);
    CP_COMMIT();

    __syncthreads();

    // stage-2: broadcast LDS of 8 warp partials (4 x float4) + 7-fadd2 tree
    float4 q0 = s_red4[pb*4 + 0], q1 = s_red4[pb*4 + 1];
    float4 q2 = s_red4[pb*4 + 2], q3 = s_red4[pb*4 + 3];
    float2 sA = fadd2(make_float2(q0.x, q0.y), make_float2(q0.z, q0.w));
    float2 sB = fadd2(make_float2(q1.x, q1.y), make_float2(q1.z, q1.w));
    float2 sC = fadd2(make_float2(q2.x, q2.y), make_float2(q2.z, q2.w));
    float2 sD = fadd2(make_float2(q3.x, q3.y), make_float2(q3.z, q3.w));
    float2 zz = fadd2(fadd2(sA, sB), fadd2(sC, sD));
    const float2 z0_2 = make_float2(zz.x, zz.x), z1_2 = make_float2(zz.y, zz.y);

    float2 az0 = make_float2(0,0), az1 = az0, ao0 = az0, ao1 = az0;
    #pragma unroll
    for (int p = 0; p < PAIRS; p++) {
      float2 tzz = ffma2(z1_2, ma1p[p], pre[p]);
      float2 acc = ffma2(z0_2, ma0p[p], tzz);
      hh[p] = acc;
      float2 r2 = tanh2s(acc);
      az0 = ffma2(r2, n0p[p], az0);
      az1 = ffma2(r2, n1p[p], az1);
      ao0 = ffma2(r2, wo0p[p], ao0);
      ao1 = ffma2(r2, wo1p[p], ao1);
    }
    pz0 = az0.x + az0.y; pz1 = az1.x + az1.y;
    // per-thread output partial straight to scratch (no in-loop reduction)
    scr[(size_t)t * NTHREADS] = make_float2(ao0.x + ao0.y, ao1.x + ao1.y);
  }
}

// pass 2: out[b,t,:] = sum over 256 threads of per-thread partials.
// one warp per (b,t): each lane sums 8 float2 (4 global float4 loads), then butterfly.
__global__ void __launch_bounds__(256, 8)
out_reduce(float* __restrict__ out)
{
  const int warp = threadIdx.x >> 5;
  const int lane = threadIdx.x & 31;
  const int i = blockIdx.x * 8 + warp;           // (b,t) pair, 32*1000 total
  if (i >= 32 * TT) return;
  const float4* p = reinterpret_cast<const float4*>(g_scratch + (size_t)i * (NTHREADS * 2)) + lane * 4;
  float4 a = p[0], c = p[1], d = p[2], e = p[3];
  float o0 = (a.x + a.z) + (c.x + c.z) + (d.x + d.z) + (e.x + e.z);
  float o1 = (a.y + a.w) + (c.y + c.w) + (d.y + d.w) + (e.y + e.w);
  #pragma unroll
  for (int o = 16; o > 0; o >>= 1) {
    o0 += __shfl_xor_sync(0xffffffffu, o0, o);
    o1 += __shfl_xor_sync(0xffffffffu, o1, o);
  }
  if (lane == 0)
    reinterpret_cast<float2*>(out)[i] = make_float2(o0, o1);
}

extern "C" void kernel_launch(void* const* d_in, const int* in_sizes, int n_in,
                              void* d_out, int out_size) {
  const float* input = (const float*)d_in[0];
  const float* noise = (const float*)d_in[1];
  const float* wi_w  = (const float*)d_in[2];
  const float* m_w   = (const float*)d_in[3];
  const float* n_w   = (const float*)d_in[4];
  const float* wo_w  = (const float*)d_in[5];
  const float* wi_b  = (const float*)d_in[6];
  const float* m_b   = (const float*)d_in[7];
  const float* n_b   = (const float*)d_in[8];
  const float* h0_w  = (const float*)d_in[9];
  const float* basis = (const float*)d_in[10];
  const float* sup   = (const float*)d_in[11];
  float* out = (float*)d_out;

  cudaFuncSetAttribute(rnn_main, cudaFuncAttributeMaxDynamicSharedMemorySize, SMEM_BYTES);
  rnn_main<<<32, NTHREADS, SMEM_BYTES>>>(input, noise, wi_w, m_w, n_w, wo_w,
                                         wi_b, m_b, n_b, h0_w, basis, sup);
  out_reduce<<<(32 * TT + 7) / 8, 256>>>(out);
}